// round 16
// baseline (speedup 1.0000x reference)
#include <cuda_runtime.h>
#include <cstdint>
#include <cstddef>

#define S_LEN   1024
#define BATCH   128
#define EDIM    256
#define HDIM    512
#define NCTA    128
#define NCTA_L0 64
#define NTHR    128
#define PA      68          // A-chunk smem pitch (floats), 68 mod 32 = 4 -> conflict free
#define PZ      36          // z smem pitch

// ---------------- persistent global staging (rewritten every launch) ----------------
__device__ __align__(16) float g_A0[2][BATCH][EDIM + HDIM];   // [xe | h0]
__device__ __align__(16) float g_A1[2][BATCH][2 * HDIM];      // [h0 | h1]
__device__ __align__(16) float g_h1f[BATCH][HDIM];            // full-precision h1 (last write wins)
__device__ unsigned g_cnt = 0;
__device__ volatile unsigned g_gen = 0;

// ---------------- helpers ----------------
__device__ __forceinline__ float f2tf_f(float f) {
    unsigned u; asm("cvt.rna.tf32.f32 %0, %1;" : "=r"(u) : "f"(f));
    return __uint_as_float(u);
}
__device__ __forceinline__ void cp16(uint32_t saddr, const float* gptr) {
    asm volatile("cp.async.cg.shared.global [%0], [%1], 16;" :: "r"(saddr), "l"(gptr));
}
__device__ __forceinline__ void cp_commit() { asm volatile("cp.async.commit_group;"); }
__device__ __forceinline__ void cp_wait0()  { asm volatile("cp.async.wait_group 0;"); }
__device__ __forceinline__ void cp_wait1()  { asm volatile("cp.async.wait_group 1;"); }

__device__ __forceinline__ void mma8(float& d0, float& d1, float& d2, float& d3,
                                     unsigned a0, unsigned a1, unsigned a2, unsigned a3,
                                     unsigned b0, unsigned b1) {
    asm volatile(
        "mma.sync.aligned.m16n8k8.row.col.f32.tf32.tf32.f32 "
        "{%0,%1,%2,%3},{%4,%5,%6,%7},{%8,%9},{%0,%1,%2,%3};"
        : "+f"(d0), "+f"(d1), "+f"(d2), "+f"(d3)
        : "r"(a0), "r"(a1), "r"(a2), "r"(a3), "r"(b0), "r"(b1));
}

__device__ __forceinline__ float sigm(float x) { return 1.0f / (1.0f + __expf(-x)); }

// Sense-reversing grid barrier. All 128 CTAs co-resident (1 CTA/SM via smem).
__device__ __forceinline__ void gbar() {
    __syncthreads();
    if (threadIdx.x == 0) {
        unsigned gen = g_gen;
        __threadfence();
        if (atomicAdd(&g_cnt, 1u) == NCTA - 1) {
            atomicExch(&g_cnt, 0u);
            __threadfence();
            g_gen = gen + 1u;
        } else {
            while (g_gen == gen) { __nanosleep(32); }
            __threadfence();
        }
    }
    __syncthreads();
}

// SMEM (worst case layer 1, PW=1028):
//   W 32*1028 + A 2*128*68 + Z 128*36 + H 1024 + bias 32 = 55968 floats = 223872 B
#define SMEM_BYTES ((32 * 1028 + 2 * BATCH * PA + BATCH * PZ + 1024 + 32) * 4)

extern "C" __global__ void __launch_bounds__(NTHR, 1)
hybrid_qlstm_kernel(const int* __restrict__ x, const float* __restrict__ emb,
                    const float* __restrict__ W0, const float* __restrict__ b0,
                    const float* __restrict__ bb0, const float* __restrict__ W1,
                    const float* __restrict__ b1, const float* __restrict__ bb1,
                    const float* __restrict__ fcw, const float* __restrict__ fcb,
                    float* __restrict__ out)
{
    extern __shared__ float sm[];
    const int cta  = blockIdx.x;
    const int tid  = threadIdx.x;
    const int lane = tid & 31;
    const int warp = tid >> 5;
    const int g    = lane >> 2;           // mma group id
    const int c4   = lane & 3;            // mma thread-in-group
    const bool is0 = (cta < NCTA_L0);
    const int  K   = is0 ? (EDIM + HDIM) : (2 * HDIM);   // 768 / 1024
    const int  PW  = K + 4;
    const int  NC  = K >> 6;                             // 12 / 16 chunks
    const int  lcta = is0 ? cta : (cta - NCTA_L0);
    const int  u0   = lcta * 8;                          // hidden-unit base
    const float* Wg  = is0 ? W0 : W1;
    const float* bg  = is0 ? b0 : b1;
    const float* bbg = is0 ? bb0 : bb1;

    float* Ws  = sm;                         // [32][PW] tf32 weights, row r = gate(r>>3), unit u0+(r&7)
    float* Ab0 = sm + 32 * PW;               // A chunk double buffer
    float* Ab1 = Ab0 + BATCH * PA;
    float* Zs  = Ab1 + BATCH * PA;           // [128][PZ] pre-activations
    float* Hs  = Zs + BATCH * PZ;            // [128][8] fresh h values
    float* Bs  = Hs + BATCH * 8;             // [32] bias

    // ---------------- prologue ----------------
    for (int r = 0; r < 32; ++r) {
        const int grow = (r >> 3) * HDIM + u0 + (r & 7);
        const float* src = Wg + (size_t)grow * K;
        for (int i = tid; i < K; i += NTHR)
            Ws[r * PW + i] = f2tf_f(src[i]);
    }
    if (tid < 32) {
        const int grow = (tid >> 3) * HDIM + u0 + (tid & 7);
        Bs[tid] = bg[grow] + bbg[grow];
    }
    // zero initial-state regions: h0[-1] in A0[0], h1[-1] in A1[1]
    for (int i = cta * NTHR + tid; i < BATCH * HDIM; i += NCTA * NTHR) {
        const int b = i >> 9, c = i & 511;
        g_A0[0][b][EDIM + c] = 0.0f;
        g_A1[1][b][HDIM + c] = 0.0f;
    }
    // xe[0]: layer-0 CTA `lcta` owns embedding columns [4*lcta, 4*lcta+4)
    if (is0) {
        const int e0 = lcta * 4;
        const int tok = x[(size_t)tid * S_LEN + 0];
        const float4 v = *(const float4*)(emb + (size_t)tok * EDIM + e0);
        float* dst = &g_A0[0][tid][e0];
        dst[0] = f2tf_f(v.x); dst[1] = f2tf_f(v.y);
        dst[2] = f2tf_f(v.z); dst[3] = f2tf_f(v.w);
    }
    float creg[8];
#pragma unroll
    for (int u = 0; u < 8; ++u) creg[u] = 0.0f;

    gbar();

    // ---------------- main recurrence: S+1 pipelined iterations ----------------
    for (int k = 0; k <= S_LEN; ++k) {
        const int cb = k & 1, nb = cb ^ 1;
        const bool active = is0 ? (k < S_LEN) : (k >= 1);

        // gather xe[k+1] into A0[nb] (layer-0 CTAs; overlaps with GEMM latency)
        if (is0 && (k + 1) < S_LEN) {
            const int e0 = lcta * 4;
            const int tok = x[(size_t)tid * S_LEN + (k + 1)];
            const float4 v = *(const float4*)(emb + (size_t)tok * EDIM + e0);
            float* dst = &g_A0[nb][tid][e0];
            dst[0] = f2tf_f(v.x); dst[1] = f2tf_f(v.y);
            dst[2] = f2tf_f(v.z); dst[3] = f2tf_f(v.w);
        }

        if (active) {
            const float* Ag = is0 ? &g_A0[cb][0][0] : &g_A1[cb][0][0];  // row stride = K
            float acc[2][4][4];
#pragma unroll
            for (int mt = 0; mt < 2; ++mt)
#pragma unroll
                for (int nt = 0; nt < 4; ++nt)
#pragma unroll
                    for (int r = 0; r < 4; ++r) acc[mt][nt][r] = 0.0f;

            // prefetch chunk 0
            {
#pragma unroll
                for (int i = 0; i < 16; ++i) {
                    const int idx = tid + i * NTHR;
                    const int row = idx >> 4, f4 = idx & 15;
                    cp16((uint32_t)__cvta_generic_to_shared(Ab0 + row * PA + f4 * 4),
                         Ag + (size_t)row * K + f4 * 4);
                }
                cp_commit();
            }

            for (int ch = 0; ch < NC; ++ch) {
                float* Acur = (ch & 1) ? Ab1 : Ab0;
                if (ch + 1 < NC) {
                    float* Anext = (ch & 1) ? Ab0 : Ab1;
                    const int kc = (ch + 1) << 6;
#pragma unroll
                    for (int i = 0; i < 16; ++i) {
                        const int idx = tid + i * NTHR;
                        const int row = idx >> 4, f4 = idx & 15;
                        cp16((uint32_t)__cvta_generic_to_shared(Anext + row * PA + f4 * 4),
                             Ag + (size_t)row * K + kc + f4 * 4);
                    }
                    cp_commit();
                    cp_wait1();
                } else {
                    cp_wait0();
                }
                __syncthreads();

                // compute on Acur against weight columns [ch*64, ch*64+64)
                const float* Wc = Ws + (ch << 6);
#pragma unroll
                for (int kk = 0; kk < 64; kk += 8) {
                    unsigned bfr[4][2];
#pragma unroll
                    for (int nt = 0; nt < 4; ++nt) {
                        const float* bp = Wc + (nt * 8 + g) * PW + kk + c4;
                        bfr[nt][0] = __float_as_uint(bp[0]);
                        bfr[nt][1] = __float_as_uint(bp[4]);
                    }
#pragma unroll
                    for (int mt = 0; mt < 2; ++mt) {
                        const float* ap = Acur + (warp * 32 + mt * 16 + g) * PA + kk + c4;
                        const unsigned a0 = __float_as_uint(ap[0]);
                        const unsigned a1 = __float_as_uint(ap[8 * PA]);
                        const unsigned a2 = __float_as_uint(ap[4]);
                        const unsigned a3 = __float_as_uint(ap[8 * PA + 4]);
#pragma unroll
                        for (int nt = 0; nt < 4; ++nt)
                            mma8(acc[mt][nt][0], acc[mt][nt][1], acc[mt][nt][2], acc[mt][nt][3],
                                 a0, a1, a2, a3, bfr[nt][0], bfr[nt][1]);
                    }
                }
                __syncthreads();
            }

            // dump accumulators -> Zs  (warp owns batch rows [32w, 32w+32))
#pragma unroll
            for (int mt = 0; mt < 2; ++mt)
#pragma unroll
                for (int nt = 0; nt < 4; ++nt) {
                    const int m = warp * 32 + mt * 16 + g;
                    const int n = nt * 8 + c4 * 2;
                    *(float2*)&Zs[m * PZ + n]       = make_float2(acc[mt][nt][0], acc[mt][nt][1]);
                    *(float2*)&Zs[(m + 8) * PZ + n] = make_float2(acc[mt][nt][2], acc[mt][nt][3]);
                }
            __syncthreads();

            // cell update: thread tid owns batch row b=tid, 8 hidden units
            {
                const int b = tid;
#pragma unroll
                for (int u = 0; u < 8; ++u) {
                    const float zf = Zs[b * PZ + u]      + Bs[u];
                    const float zi = Zs[b * PZ + 8 + u]  + Bs[8 + u];
                    const float zc = Zs[b * PZ + 16 + u] + Bs[16 + u];
                    const float zo = Zs[b * PZ + 24 + u] + Bs[24 + u];
                    const float fg = sigm(zf);
                    const float ig = sigm(zi);
                    const float ct = tanhf(zc);
                    const float og = sigm(zo);
                    const float cc = fg * creg[u] + ig * ct;
                    creg[u] = cc;
                    Hs[b * 8 + u] = og * tanhf(cc);
                }
            }
            __syncthreads();

            // coalesced global h writes (tf32-rounded for the GEMM path)
#pragma unroll
            for (int i = 0; i < 4; ++i) {
                const int idx = tid + i * NTHR;         // 0..511
                const int b = idx >> 2, j = (idx & 3) * 2;
                const float h0v = Hs[b * 8 + j];
                const float h1v = Hs[b * 8 + j + 1];
                const float2 hv = make_float2(f2tf_f(h0v), f2tf_f(h1v));
                if (is0) {
                    *(float2*)&g_A0[nb][b][EDIM + u0 + j] = hv;
                    *(float2*)&g_A1[nb][b][u0 + j]        = hv;
                } else {
                    *(float2*)&g_A1[nb][b][HDIM + u0 + j] = hv;
                    *(float2*)&g_h1f[b][u0 + j]           = make_float2(h0v, h1v);
                }
            }
        }
        gbar();
    }

    // ---------------- epilogue FC: out[b][j] = h1[b] . fcw[j] + fcb[j] ----------------
    if (cta == 0) {
        const int b = tid;
        float s0 = 0.0f, s1 = 0.0f;
        for (int u = 0; u < HDIM; ++u) {
            const float h = g_h1f[b][u];
            s0 += h * fcw[u];
            s1 += h * fcw[HDIM + u];
        }
        out[b * 2 + 0] = s0 + fcb[0];
        out[b * 2 + 1] = s1 + fcb[1];
    }
}

extern "C" void kernel_launch(void* const* d_in, const int* in_sizes, int n_in,
                              void* d_out, int out_size) {
    (void)in_sizes; (void)n_in; (void)out_size;
    cudaFuncSetAttribute(hybrid_qlstm_kernel,
                         cudaFuncAttributeMaxDynamicSharedMemorySize, SMEM_BYTES);
    hybrid_qlstm_kernel<<<NCTA, NTHR, SMEM_BYTES>>>(
        (const int*)d_in[0],  (const float*)d_in[1], (const float*)d_in[2],
        (const float*)d_in[3], (const float*)d_in[4], (const float*)d_in[5],
        (const float*)d_in[6], (const float*)d_in[7], (const float*)d_in[8],
        (const float*)d_in[9], (float*)d_out);
}